// round 12
// baseline (speedup 1.0000x reference)
#include <cuda_runtime.h>

#define BB    8
#define NMAX  128
#define HH    192
#define WW    256
#define INV_DOWN 0.125f
#define NBOX   (BB * NMAX)     // 1024 boxes
#define WPB    4               // warps (=boxes) per CTA
#define GRIDB  (NBOX / WPB)    // 256 CTAs
#define NCX    7               // float4 chunks per row (covers <=25 aligned cols)
#define SLOTS  5               // chunk slots per lane: 5*32=160 >= 7*22=154

// Antiderivative of the bilinear hat kernel, clipped to [-1, 1] (branchless)
__device__ __forceinline__ float hatP(float u) {
    u = fminf(1.0f, fmaxf(-1.0f, u));
    float neg = 0.5f * (u + 1.0f) * (u + 1.0f);
    float pos = 0.5f + u - 0.5f * u * u;
    return (u <= 0.0f) ? neg : pos;
}

__global__ __launch_bounds__(WPB * 32)
void count_kernel(const float* __restrict__ den,     // [B, 1, H, W]
                  const float* __restrict__ hboxes,  // [B, NMAX, 5]
                  const float* __restrict__ post,    // [B, NMAX, H, W]
                  float* __restrict__ out)           // zeroed by memset node
{
    const int w    = threadIdx.x >> 5;
    const int lane = threadIdx.x & 31;
    const int bn   = blockIdx.x * WPB + w;      // this warp's box
    const int b    = bn >> 7;                   // image index

    // All scalar loads issued up-front (one L2/DRAM round-trip, MLP=9).
    const float* box = hboxes + (size_t)bn * 5;
    const float bx1 = __ldg(box + 0);
    const float by1 = __ldg(box + 1);
    const float bx2 = __ldg(box + 2);
    const float by2 = __ldg(box + 3);
    const float lab = __ldg(box + 4);

    const float* labB = hboxes + (size_t)b * NMAX * 5 + 4;
    const float l0 = __ldg(labB + (lane      ) * 5);
    const float l1 = __ldg(labB + (lane + 32 ) * 5);
    const float l2 = __ldg(labB + (lane + 64 ) * 5);
    const float l3 = __ldg(labB + (lane + 96 ) * 5);

    if (lab <= 0.0f) return;        // uniform per warp; zero barriers in kernel

    const int num = __popc(__ballot_sync(0xffffffffu, l0 > 0.0f))
                  + __popc(__ballot_sync(0xffffffffu, l1 > 0.0f))
                  + __popc(__ballot_sync(0xffffffffu, l2 > 0.0f))
                  + __popc(__ballot_sync(0xffffffffu, l3 > 0.0f));   // >= 1

    const float x1 = bx1 * INV_DOWN;
    const float y1 = by1 * INV_DOWN;
    const float x2 = bx2 * INV_DOWN;
    const float y2 = by2 * INV_DOWN;

    const int ix0 = max(0, (int)floorf(x1) - 1);
    const int ix1 = min(WW - 1, (int)ceilf(x2) + 1);
    const int iy0 = max(0, (int)floorf(y1) - 1);
    const int iy1 = min(HH - 1, (int)ceilf(y2) + 1);
    const int ny  = iy1 - iy0 + 1;       // <= 22
    const int ax0 = ix0 & ~3;            // 16B-aligned x origin (left pad weight==0)
    const int nslots = NCX * ny;         // <= 154 <= 160

    const float* denB  = den  + (size_t)b  * (HH * WW);
    const float* postN = post + (size_t)bn * (HH * WW);

    // Batch all 10 vector loads (5 slots x {den, post}) -> high MLP, few issues.
    float4 dv[SLOTS], pv[SLOTS];
    int    xb[SLOTS], yy[SLOTS];
    bool   vs[SLOTS];
    #pragma unroll
    for (int s = 0; s < SLOTS; s++) {
        const int cid = lane + s * 32;
        const int cy  = cid / NCX;           // constant divisor -> magic mul
        const int cx  = cid - cy * NCX;
        vs[s] = (cid < nslots);
        const int cyc = vs[s] ? cy : 0;
        yy[s] = iy0 + cyc;
        xb[s] = ax0 + cx * 4;                // intended x of element 0
        const int addrx = min(xb[s], WW - 4);   // clamp: clamped cells have w=0
        const int idx = yy[s] * WW + addrx;
        dv[s] = *(const float4*)(denB  + idx);
        pv[s] = *(const float4*)(postN + idx);
    }

    float acc = 0.0f;
    #pragma unroll
    for (int s = 0; s < SLOTS; s++) {
        const float fy  = (float)yy[s];
        float wyv = hatP(y2 - fy) - hatP(y1 - fy);
        wyv = vs[s] ? wyv : 0.0f;

        float rowsum = 0.0f;
        const float dd[4] = {dv[s].x, dv[s].y, dv[s].z, dv[s].w};
        const float pp[4] = {pv[s].x, pv[s].y, pv[s].z, pv[s].w};
        #pragma unroll
        for (int e = 0; e < 4; e++) {
            const int   xi = xb[s] + e;                 // intended x
            const float fx = (float)xi;
            float wxv = hatP(x2 - fx) - hatP(x1 - fx);  // 0 for x < ix0 by clipping
            wxv = (xi <= ix1) ? wxv : 0.0f;             // 0 for right overhang/clamped
            rowsum += wxv * (dd[e] * pp[e]);
        }
        acc += wyv * rowsum;
    }

    // Warp reduce, one RED per box. No smem, no bar.sync.
    #pragma unroll
    for (int o = 16; o > 0; o >>= 1)
        acc += __shfl_down_sync(0xffffffffu, acc, o);

    if (lane == 0)
        atomicAdd(out, fabsf(acc - 1.0f) * (1.0f / (float)num));
}

extern "C" void kernel_launch(void* const* d_in, const int* in_sizes, int n_in,
                              void* d_out, int out_size)
{
    // metadata order: cls(0), reg(1), off(2), den(3), fboxes(4), hboxes(5),
    //                 ctr_masks(6), post_probs(7)
    const float* den    = (const float*)d_in[3];
    const float* hboxes = (const float*)d_in[5];
    const float* post   = (const float*)d_in[7];
    float* out = (float*)d_out;

    cudaMemsetAsync(out, 0, sizeof(float));          // graph memset node
    count_kernel<<<GRIDB, WPB * 32>>>(den, hboxes, post, out);
}

// round 13
// speedup vs baseline: 1.0237x; 1.0237x over previous
#include <cuda_runtime.h>

#define BB    8
#define NMAX  128
#define HH    192
#define WW    256
#define INV_DOWN 0.125f
#define NBOX   (BB * NMAX)     // 1024 boxes
#define WPB    4               // warps (=boxes) per CTA
#define GRIDB  (NBOX / WPB)    // 256 CTAs
#define CMAX   13              // max cells/lane: 13*32 = 416 >= 20*20 = 400
#define CSMALL 8               // fast path: 8*32 = 256

// Antiderivative of the bilinear hat kernel, clipped to [-1, 1] (branchless)
__device__ __forceinline__ float hatP(float u) {
    u = fminf(1.0f, fmaxf(-1.0f, u));
    float neg = 0.5f * (u + 1.0f) * (u + 1.0f);
    float pos = 0.5f + u - 0.5f * u * u;
    return (u <= 0.0f) ? neg : pos;
}

// Loop-free region accumulate: NC predicated cells per lane, all loads batched.
template <int NC>
__device__ __forceinline__ float region_acc(
    int lane, int total, int nx, unsigned magic,
    int ix0, int iy0,
    float x1, float x2, float y1, float y2,
    const float* __restrict__ denB, const float* __restrict__ postN)
{
    float dv[NC], pv[NC];
    #pragma unroll
    for (int i = 0; i < NC; i++) {
        const int k  = lane + i * 32;
        const int jy = (int)__umulhi((unsigned)k, magic);
        const int jx = k - jy * nx;
        const int idx = (iy0 + jy) * WW + (ix0 + jx);
        const bool m = (k < total);
        dv[i] = m ? __ldg(denB  + idx) : 0.0f;
        pv[i] = m ? __ldg(postN + idx) : 0.0f;
    }
    float a0 = 0.0f, a1 = 0.0f;
    #pragma unroll
    for (int i = 0; i < NC; i++) {
        const int k  = lane + i * 32;
        const int jy = (int)__umulhi((unsigned)k, magic);
        const int jx = k - jy * nx;
        const float fx = (float)(ix0 + jx);
        const float fy = (float)(iy0 + jy);
        const float wxv = hatP(x2 - fx) - hatP(x1 - fx);
        const float wyv = hatP(y2 - fy) - hatP(y1 - fy);
        const float v = (wxv * wyv) * (dv[i] * pv[i]);
        if (i & 1) a1 += v; else a0 += v;
    }
    return a0 + a1;
}

__global__ __launch_bounds__(WPB * 32)
void count_kernel(const float* __restrict__ den,     // [B, 1, H, W]
                  const float* __restrict__ hboxes,  // [B, NMAX, 5]
                  const float* __restrict__ post,    // [B, NMAX, H, W]
                  float* __restrict__ out)           // zeroed by memset node
{
    const int w    = threadIdx.x >> 5;
    const int lane = threadIdx.x & 31;
    const int bn   = blockIdx.x * WPB + w;      // this warp's box
    const int b    = bn >> 7;                   // image index

    // All scalar loads issued up-front (one round-trip, MLP=9).
    const float* box = hboxes + (size_t)bn * 5;
    const float bx1 = __ldg(box + 0);
    const float by1 = __ldg(box + 1);
    const float bx2 = __ldg(box + 2);
    const float by2 = __ldg(box + 3);
    const float lab = __ldg(box + 4);

    const float* labB = hboxes + (size_t)b * NMAX * 5 + 4;   // label stride 5
    const float l0 = __ldg(labB + (lane      ) * 5);
    const float l1 = __ldg(labB + (lane + 32 ) * 5);
    const float l2 = __ldg(labB + (lane + 64 ) * 5);
    const float l3 = __ldg(labB + (lane + 96 ) * 5);

    if (lab <= 0.0f) return;        // uniform per warp; zero barriers in kernel

    const int num = __popc(__ballot_sync(0xffffffffu, l0 > 0.0f))
                  + __popc(__ballot_sync(0xffffffffu, l1 > 0.0f))
                  + __popc(__ballot_sync(0xffffffffu, l2 > 0.0f))
                  + __popc(__ballot_sync(0xffffffffu, l3 > 0.0f));   // >= 1

    const float x1 = bx1 * INV_DOWN;
    const float y1 = by1 * INV_DOWN;
    const float x2 = bx2 * INV_DOWN;
    const float y2 = by2 * INV_DOWN;

    // Tight support: weight at floor(lo)-1 and ceil(hi)+1 is exactly 0
    // (both antiderivative args clip), so no padding needed.
    const int ix0 = max(0, (int)floorf(x1));
    const int ix1 = min(WW - 1, (int)ceilf(x2));
    const int iy0 = max(0, (int)floorf(y1));
    const int iy1 = min(HH - 1, (int)ceilf(y2));
    const int nx = ix1 - ix0 + 1;   // <= 20
    const int ny = iy1 - iy0 + 1;   // <= 20
    const int total = nx * ny;      // <= 400 <= CMAX*32

    // Magic divide: jy = k / nx via umulhi, exact for k < 2^16.
    const unsigned magic =
        (unsigned)(((1ull << 32) + (unsigned)nx - 1) / (unsigned)nx);

    const float* denB  = den  + (size_t)b  * (HH * WW);
    const float* postN = post + (size_t)bn * (HH * WW);

    // Warp-uniform branch: common small boxes take the 8-slot path.
    float acc;
    if (total <= CSMALL * 32)
        acc = region_acc<CSMALL>(lane, total, nx, magic, ix0, iy0,
                                 x1, x2, y1, y2, denB, postN);
    else
        acc = region_acc<CMAX>(lane, total, nx, magic, ix0, iy0,
                               x1, x2, y1, y2, denB, postN);

    // Warp reduce, one RED per box. No smem, no bar.sync.
    #pragma unroll
    for (int o = 16; o > 0; o >>= 1)
        acc += __shfl_down_sync(0xffffffffu, acc, o);

    if (lane == 0)
        atomicAdd(out, fabsf(acc - 1.0f) * (1.0f / (float)num));
}

extern "C" void kernel_launch(void* const* d_in, const int* in_sizes, int n_in,
                              void* d_out, int out_size)
{
    // metadata order: cls(0), reg(1), off(2), den(3), fboxes(4), hboxes(5),
    //                 ctr_masks(6), post_probs(7)
    const float* den    = (const float*)d_in[3];
    const float* hboxes = (const float*)d_in[5];
    const float* post   = (const float*)d_in[7];
    float* out = (float*)d_out;

    cudaMemsetAsync(out, 0, sizeof(float));          // graph memset node
    count_kernel<<<GRIDB, WPB * 32>>>(den, hboxes, post, out);
}